// round 3
// baseline (speedup 1.0000x reference)
#include <cuda_runtime.h>
#include <cstdint>
#include <cstddef>

namespace {

constexpr int S = 1024;
constexpr int D = 64;
constexpr int QT = 16;           // queries per block
constexpr int KT = 64;           // keys per tile
constexpr int NT = S / KT;       // 16 tiles
constexpr int THREADS = 256;
constexpr int PAD = 68;          // floats per smem row (17 float4, conflict-free)
constexpr float SCALE = 0.125f;  // 1/sqrt(64)

__device__ __forceinline__ void cp16(void* smem, const void* gmem) {
    unsigned sa = (unsigned)__cvta_generic_to_shared(smem);
    asm volatile("cp.async.cg.shared.global [%0], [%1], 16;" :: "r"(sa), "l"(gmem));
}
__device__ __forceinline__ void cp_commit() {
    asm volatile("cp.async.commit_group;" ::: "memory");
}
template <int N>
__device__ __forceinline__ void cp_wait() {
    asm volatile("cp.async.wait_group %0;" :: "n"(N) : "memory");
}

__global__ void __launch_bounds__(THREADS, 2)
sdpa_kernel(const float* __restrict__ Qg_, const float* __restrict__ Kg_,
            const float* __restrict__ Vg_, const uint8_t* __restrict__ Mg_,
            float* __restrict__ Octx, float* __restrict__ Oattn)
{
    __shared__ __align__(16) float sQ[QT * PAD];
    __shared__ __align__(16) float sKV[2][KT * PAD];
    __shared__ __align__(16) float sP[QT * PAD];
    __shared__ float sRed[2][QT][2];

    const int tid  = threadIdx.x;
    const int lane = tid & 31;
    const int w    = tid >> 5;
    const int half = w & 1;
    const int qg   = tid >> 6;    // 0..3 -> q rows 4*qg .. 4*qg+3 (QK mapping)
    const int kk   = tid & 63;    // key column within tile (QK mapping)

    const int bh = blockIdx.y;
    const int q0 = blockIdx.x * QT;

    // ---- mask layout detection (1-byte bool vs 4-byte int32/float32) ----
    // Sample bytes at offsets 1 mod 4 in the first 512 bytes of the mask
    // buffer (in-bounds under either layout). For a 4-byte 0/1 (or 0.0/1.0)
    // mask these bytes are always 0; for a random 1-byte bool mask, P(all
    // 128 samples zero) ~= 2^-128.
    int pred = (tid < 128) ? (Mg_[4 * tid + 1] != 0) : 0;
    const bool mask1B = (__syncthreads_or(pred) != 0);

    const float*   Qg = Qg_ + ((size_t)bh * S + q0) * D;
    const float*   Kg = Kg_ + (size_t)bh * S * D;
    const float*   Vg = Vg_ + (size_t)bh * S * D;
    const uint8_t* Mg8  = Mg_ + ((size_t)bh * S + q0) * (size_t)S;
    const int*     Mg32 = (const int*)Mg_ + ((size_t)bh * S + q0) * (size_t)S;

    // ---- load Q tile (pre-scaled) ----
    for (int i = tid; i < QT * D; i += THREADS) {
        sQ[(i >> 6) * PAD + (i & 63)] = Qg[i] * SCALE;
    }

    // ---- prefetch K tile 0 ----
    #pragma unroll
    for (int j = 0; j < 4; j++) {
        int i = tid + j * THREADS;                       // float4 id 0..1023
        cp16(&sKV[0][(i >> 4) * PAD + (i & 15) * 4], Kg + (size_t)i * 4);
    }
    cp_commit();

    float sc[NT * 4];  // raw scores -> exp values, kept in registers

    // ================= Phase 1: S = (Q*scale) K^T, masked =================
    #pragma unroll
    for (int t = 0; t < NT; t++) {
        __syncthreads();  // everyone done with buffer (t+1)&1 before refill
        const float* nxt = (t + 1 < NT) ? (Kg + (size_t)(t + 1) * KT * D) : Vg;
        #pragma unroll
        for (int j = 0; j < 4; j++) {
            int i = tid + j * THREADS;
            cp16(&sKV[(t + 1) & 1][(i >> 4) * PAD + (i & 15) * 4], nxt + (size_t)i * 4);
        }
        cp_commit();
        cp_wait<1>();     // tile t resident
        __syncthreads();

        const float4* kb  = reinterpret_cast<const float4*>(&sKV[t & 1][kk * PAD]);
        const float4* qp0 = reinterpret_cast<const float4*>(&sQ[(4 * qg + 0) * PAD]);
        const float4* qp1 = reinterpret_cast<const float4*>(&sQ[(4 * qg + 1) * PAD]);
        const float4* qp2 = reinterpret_cast<const float4*>(&sQ[(4 * qg + 2) * PAD]);
        const float4* qp3 = reinterpret_cast<const float4*>(&sQ[(4 * qg + 3) * PAD]);

        float s0 = 0.f, s1 = 0.f, s2 = 0.f, s3 = 0.f;
        #pragma unroll 4
        for (int d4 = 0; d4 < 16; d4++) {
            float4 k4 = kb[d4];
            float4 a;
            a = qp0[d4]; s0 += a.x*k4.x; s0 += a.y*k4.y; s0 += a.z*k4.z; s0 += a.w*k4.w;
            a = qp1[d4]; s1 += a.x*k4.x; s1 += a.y*k4.y; s1 += a.z*k4.z; s1 += a.w*k4.w;
            a = qp2[d4]; s2 += a.x*k4.x; s2 += a.y*k4.y; s2 += a.z*k4.z; s2 += a.w*k4.w;
            a = qp3[d4]; s3 += a.x*k4.x; s3 += a.y*k4.y; s3 += a.z*k4.z; s3 += a.w*k4.w;
        }
        int m0, m1, m2, m3;
        if (mask1B) {
            const uint8_t* mrow = Mg8 + t * KT + kk;
            m0 = mrow[(4*qg+0) * S]; m1 = mrow[(4*qg+1) * S];
            m2 = mrow[(4*qg+2) * S]; m3 = mrow[(4*qg+3) * S];
        } else {
            const int* mrow = Mg32 + t * KT + kk;
            m0 = mrow[(4*qg+0) * S]; m1 = mrow[(4*qg+1) * S];
            m2 = mrow[(4*qg+2) * S]; m3 = mrow[(4*qg+3) * S];
        }
        sc[t*4+0] = m0 ? -1e9f : s0;
        sc[t*4+1] = m1 ? -1e9f : s1;
        sc[t*4+2] = m2 ? -1e9f : s2;
        sc[t*4+3] = m3 ? -1e9f : s3;
    }

    // ================= Phase 2: softmax over full row =================
    #pragma unroll
    for (int qi = 0; qi < 4; qi++) {
        float m = -3.4e38f;
        #pragma unroll
        for (int t = 0; t < NT; t++) m = fmaxf(m, sc[t*4+qi]);
        #pragma unroll
        for (int o = 16; o; o >>= 1) m = fmaxf(m, __shfl_xor_sync(0xffffffffu, m, o));
        if (lane == 0) sRed[0][4*qg+qi][half] = m;
    }
    __syncthreads();
    #pragma unroll
    for (int qi = 0; qi < 4; qi++) {
        float m = fmaxf(sRed[0][4*qg+qi][0], sRed[0][4*qg+qi][1]);
        float s = 0.f;
        #pragma unroll
        for (int t = 0; t < NT; t++) {
            float e = __expf(sc[t*4+qi] - m);
            sc[t*4+qi] = e;
            s += e;
        }
        #pragma unroll
        for (int o = 16; o; o >>= 1) s += __shfl_xor_sync(0xffffffffu, s, o);
        if (lane == 0) sRed[1][4*qg+qi][half] = s;
    }
    __syncthreads();

    float invr[4];
    #pragma unroll
    for (int qi = 0; qi < 4; qi++)
        invr[qi] = 1.0f / (sRed[1][4*qg+qi][0] + sRed[1][4*qg+qi][1]);

    // ================= Phase 3: attn write + context = P V =================
    // PV mapping: qg (same), ks = k-split quarter, d4 = 4-float d-chunk
    const int ks = (tid >> 4) & 3;
    const int d4 = tid & 15;

    float4 acc[4];
    #pragma unroll
    for (int i = 0; i < 4; i++) acc[i] = make_float4(0.f, 0.f, 0.f, 0.f);

    float* Ag = Oattn ? (Oattn + ((size_t)bh * S + q0) * (size_t)S) : nullptr;

    #pragma unroll
    for (int t = 0; t < NT; t++) {
        __syncthreads();  // prev sP reads done; prefetch buffer free
        if (t + 1 < NT) {
            const float* nxt = Vg + (size_t)(t + 1) * KT * D;
            #pragma unroll
            for (int j = 0; j < 4; j++) {
                int i = tid + j * THREADS;
                cp16(&sKV[(t + 1) & 1][(i >> 4) * PAD + (i & 15) * 4], nxt + (size_t)i * 4);
            }
            cp_commit();
        }
        // stage probs for this tile + write attn output (QK mapping)
        #pragma unroll
        for (int qi = 0; qi < 4; qi++) {
            float p = sc[t*4+qi] * invr[qi];
            sP[(4*qg+qi) * PAD + kk] = p;
            if (Ag) Ag[(size_t)(4*qg+qi) * S + t * KT + kk] = p;
        }
        if (t + 1 < NT) { cp_wait<1>(); } else { cp_wait<0>(); }
        __syncthreads();  // sP + V tile t visible

        const float* vb = &sKV[t & 1][0];
        #pragma unroll 4
        for (int kkk = 0; kkk < 16; kkk++) {
            int k = ks * 16 + kkk;
            float4 v = reinterpret_cast<const float4*>(vb + k * PAD)[d4];
            #pragma unroll
            for (int qi = 0; qi < 4; qi++) {
                float p = sP[(4*qg+qi) * PAD + k];
                acc[qi].x += p * v.x;
                acc[qi].y += p * v.y;
                acc[qi].z += p * v.z;
                acc[qi].w += p * v.w;
            }
        }
    }

    // ---- reduce the 4 k-split partials through smem, write context ----
    __syncthreads();
    float* sCtx = &sKV[0][0];   // 4*16*64 = 4096 floats, fits
    #pragma unroll
    for (int qi = 0; qi < 4; qi++) {
        reinterpret_cast<float4*>(&sCtx[((ks * QT + 4*qg + qi) * D) + d4 * 4])[0] = acc[qi];
    }
    __syncthreads();

    if (Octx) {
        int q  = tid >> 4;
        int dd = tid & 15;
        const float4* base = reinterpret_cast<const float4*>(sCtx);
        float4 r  = base[(0 * QT + q) * 16 + dd];
        float4 c1 = base[(1 * QT + q) * 16 + dd];
        float4 c2 = base[(2 * QT + q) * 16 + dd];
        float4 c3 = base[(3 * QT + q) * 16 + dd];
        r.x += c1.x + c2.x + c3.x;
        r.y += c1.y + c2.y + c3.y;
        r.z += c1.z + c2.z + c3.z;
        r.w += c1.w + c2.w + c3.w;
        float* Cg = Octx + ((size_t)bh * S + q0) * D;
        reinterpret_cast<float4*>(Cg)[q * 16 + dd] = r;
    }
}

} // namespace

extern "C" void kernel_launch(void* const* d_in, const int* in_sizes, int n_in,
                              void* d_out, int out_size) {
    const float*   Q = (const float*)d_in[0];
    const float*   K = (const float*)d_in[1];
    const float*   V = (const float*)d_in[2];
    const uint8_t* M = (const uint8_t*)d_in[3];

    const long long NCTX = 8LL * 16 * 1024 * 64;      // 8388608
    const long long NATT = 8LL * 16 * 1024 * 1024;    // 134217728

    float* ctx  = nullptr;
    float* attn = nullptr;
    if ((long long)out_size >= NCTX + NATT) {
        ctx  = (float*)d_out;                 // tuple order: (context, attn)
        attn = (float*)d_out + NCTX;
    } else if ((long long)out_size == NATT) {
        attn = (float*)d_out;
    } else {
        ctx = (float*)d_out;
    }

    dim3 grid(S / QT, 8 * 16);
    sdpa_kernel<<<grid, THREADS>>>(Q, K, V, M, ctx, attn);
}

// round 4
// speedup vs baseline: 1.2947x; 1.2947x over previous
#include <cuda_runtime.h>
#include <cstdint>
#include <cstddef>

namespace {

constexpr int S = 1024;
constexpr int D = 64;
constexpr int QT = 16;           // queries per block
constexpr int IT = 128;          // keys per iteration
constexpr int NI = S / IT;       // 8 iterations
constexpr int NT = 16;           // 64-key score tiles (2 per iteration)
constexpr int THREADS = 256;
constexpr int PAD = 68;          // K/V smem row stride (floats)
constexpr int PPAD = 132;        // sP row stride (floats)
constexpr float SCALE = 0.125f;  // 1/sqrt(64)

// dynamic smem layout (in floats)
constexpr int SQ_OFF   = 0;                     // 16*68  = 1088
constexpr int SKV_OFF  = SQ_OFF + QT * PAD;     // 2 buffers
constexpr int SKV_BUF  = IT * PAD;              // 8704
constexpr int SP_OFF   = SKV_OFF + 2 * SKV_BUF; // 16*132 = 2112
constexpr int SRED_OFF = SP_OFF + QT * PPAD;    // 2*16*2 = 64
constexpr int SMEM_FLOATS = SRED_OFF + 64;
constexpr int SMEM_BYTES  = SMEM_FLOATS * 4;    // 82,688 B

__device__ __forceinline__ float2 ffma2(float2 a, float2 b, float2 c) {
    unsigned long long au = *reinterpret_cast<unsigned long long*>(&a);
    unsigned long long bu = *reinterpret_cast<unsigned long long*>(&b);
    unsigned long long cu = *reinterpret_cast<unsigned long long*>(&c);
    unsigned long long du;
    asm("fma.rn.f32x2 %0, %1, %2, %3;" : "=l"(du) : "l"(au), "l"(bu), "l"(cu));
    return *reinterpret_cast<float2*>(&du);
}

__device__ __forceinline__ void cp16(void* smem, const void* gmem) {
    unsigned sa = (unsigned)__cvta_generic_to_shared(smem);
    asm volatile("cp.async.cg.shared.global [%0], [%1], 16;" :: "r"(sa), "l"(gmem));
}
__device__ __forceinline__ void cp_commit() {
    asm volatile("cp.async.commit_group;" ::: "memory");
}
template <int N>
__device__ __forceinline__ void cp_wait() {
    asm volatile("cp.async.wait_group %0;" :: "n"(N) : "memory");
}

__global__ void __launch_bounds__(THREADS, 2)
sdpa_kernel(const float* __restrict__ Qg_, const float* __restrict__ Kg_,
            const float* __restrict__ Vg_, const uint8_t* __restrict__ Mg_,
            float* __restrict__ Octx, float* __restrict__ Oattn)
{
    extern __shared__ float sm[];
    float* sQ   = sm + SQ_OFF;
    float* sKV0 = sm + SKV_OFF;
    float* sP   = sm + SP_OFF;
    float* sRed = sm + SRED_OFF;   // [2][16][2]

    const int tid  = threadIdx.x;
    const int lane = tid & 31;
    const int w    = tid >> 5;
    const int half = w & 1;
    const int qg   = tid >> 6;     // 0..3 -> q rows 4*qg..4*qg+3
    const int kk   = tid & 63;     // QK: key slot (k = kk and kk+64)
    const int d4   = tid & 15;     // PV: d chunk
    const int ks   = (tid >> 4) & 3; // PV: k split

    const int bh = blockIdx.y;
    const int q0 = blockIdx.x * QT;

    // ---- mask layout detection (1-byte bool vs 4-byte int/float) ----
    int pred = (tid < 128) ? (Mg_[4 * tid + 1] != 0) : 0;
    const bool mask1B = (__syncthreads_or(pred) != 0);

    const float*   Qg   = Qg_ + ((size_t)bh * S + q0) * D;
    const float*   Kg   = Kg_ + (size_t)bh * S * D;
    const float*   Vg   = Vg_ + (size_t)bh * S * D;
    const uint8_t* Mg8  = Mg_ + ((size_t)bh * S + q0) * (size_t)S;
    const int*     Mg32 = (const int*)Mg_ + ((size_t)bh * S + q0) * (size_t)S;

    // ---- load Q tile (pre-scaled) ----
    for (int i = tid; i < QT * D; i += THREADS)
        sQ[(i >> 6) * PAD + (i & 63)] = Qg[i] * SCALE;

    // ---- prefetch K iter 0 ----
    #pragma unroll
    for (int j = 0; j < 8; j++) {
        int i = tid + j * THREADS;                   // float4 id 0..2047
        cp16(&sKV0[(i >> 4) * PAD + (i & 15) * 4], Kg + (size_t)i * 4);
    }
    cp_commit();

    float sc[NT * 4];   // 64 scores per thread (registers)

    // ================= Phase 1: S = (Q*scale) K^T, masked =================
    #pragma unroll
    for (int it = 0; it < NI; it++) {
        __syncthreads();
        const float* nxt = (it + 1 < NI) ? (Kg + (size_t)(it + 1) * IT * D) : Vg;
        float* dstb = sKV0 + ((it + 1) & 1) * SKV_BUF;
        #pragma unroll
        for (int j = 0; j < 8; j++) {
            int i = tid + j * THREADS;
            cp16(&dstb[(i >> 4) * PAD + (i & 15) * 4], nxt + (size_t)i * 4);
        }
        cp_commit();
        cp_wait<1>();
        __syncthreads();

        const float* bufc = sKV0 + (it & 1) * SKV_BUF;
        const float4* kAp = reinterpret_cast<const float4*>(bufc + kk * PAD);
        const float4* kBp = reinterpret_cast<const float4*>(bufc + (kk + 64) * PAD);
        const float4* qp[4];
        #pragma unroll
        for (int qi = 0; qi < 4; qi++)
            qp[qi] = reinterpret_cast<const float4*>(sQ + (4 * qg + qi) * PAD);

        float2 aA[4], aB[4];
        #pragma unroll
        for (int qi = 0; qi < 4; qi++) { aA[qi] = make_float2(0.f, 0.f); aB[qi] = make_float2(0.f, 0.f); }

        #pragma unroll
        for (int dd = 0; dd < 16; dd++) {
            float4 kva = kAp[dd];
            float4 kvb = kBp[dd];
            float2 kal = make_float2(kva.x, kva.y), kah = make_float2(kva.z, kva.w);
            float2 kbl = make_float2(kvb.x, kvb.y), kbh = make_float2(kvb.z, kvb.w);
            #pragma unroll
            for (int qi = 0; qi < 4; qi++) {
                float4 q4 = qp[qi][dd];
                float2 ql = make_float2(q4.x, q4.y), qh = make_float2(q4.z, q4.w);
                aA[qi] = ffma2(ql, kal, aA[qi]);
                aA[qi] = ffma2(qh, kah, aA[qi]);
                aB[qi] = ffma2(ql, kbl, aB[qi]);
                aB[qi] = ffma2(qh, kbh, aB[qi]);
            }
        }

        const int colA = it * IT + kk;
        const int colB = colA + 64;
        #pragma unroll
        for (int qi = 0; qi < 4; qi++) {
            int row = 4 * qg + qi;
            int mA, mB;
            if (mask1B) {
                mA = Mg8[(size_t)row * S + colA];
                mB = Mg8[(size_t)row * S + colB];
            } else {
                mA = Mg32[(size_t)row * S + colA];
                mB = Mg32[(size_t)row * S + colB];
            }
            float sA = aA[qi].x + aA[qi].y;
            float sB = aB[qi].x + aB[qi].y;
            sc[(2 * it) * 4 + qi]     = mA ? -1e9f : sA;
            sc[(2 * it + 1) * 4 + qi] = mB ? -1e9f : sB;
        }
    }

    // ================= Phase 2: softmax over full row =================
    #pragma unroll
    for (int qi = 0; qi < 4; qi++) {
        float m = -3.4e38f;
        #pragma unroll
        for (int t = 0; t < NT; t++) m = fmaxf(m, sc[t * 4 + qi]);
        #pragma unroll
        for (int o = 16; o; o >>= 1) m = fmaxf(m, __shfl_xor_sync(0xffffffffu, m, o));
        if (lane == 0) sRed[(4 * qg + qi) * 2 + half] = m;
    }
    __syncthreads();
    #pragma unroll
    for (int qi = 0; qi < 4; qi++) {
        float m = fmaxf(sRed[(4 * qg + qi) * 2 + 0], sRed[(4 * qg + qi) * 2 + 1]);
        float s = 0.f;
        #pragma unroll
        for (int t = 0; t < NT; t++) {
            float e = __expf(sc[t * 4 + qi] - m);
            sc[t * 4 + qi] = e;
            s += e;
        }
        #pragma unroll
        for (int o = 16; o; o >>= 1) s += __shfl_xor_sync(0xffffffffu, s, o);
        if (lane == 0) sRed[32 + (4 * qg + qi) * 2 + half] = s;
    }
    __syncthreads();

    float invr[4];
    #pragma unroll
    for (int qi = 0; qi < 4; qi++)
        invr[qi] = 1.0f / (sRed[32 + (4 * qg + qi) * 2 + 0] + sRed[32 + (4 * qg + qi) * 2 + 1]);

    // ================= Phase 3: attn write + context = P V =================
    float2 acc0[4], acc1[4];
    #pragma unroll
    for (int qi = 0; qi < 4; qi++) { acc0[qi] = make_float2(0.f, 0.f); acc1[qi] = make_float2(0.f, 0.f); }

    float* Ag = Oattn ? (Oattn + ((size_t)bh * S + q0) * (size_t)S) : nullptr;

    #pragma unroll
    for (int it = 0; it < NI; it++) {
        __syncthreads();      // prior PV reads + sP reads done
        if (it + 1 < NI) {
            const float* nxt = Vg + (size_t)(it + 1) * IT * D;
            float* dstb = sKV0 + ((it + 1) & 1) * SKV_BUF;
            #pragma unroll
            for (int j = 0; j < 8; j++) {
                int i = tid + j * THREADS;
                cp16(&dstb[(i >> 4) * PAD + (i & 15) * 4], nxt + (size_t)i * 4);
            }
            cp_commit();
        }
        // stage normalized probs (QK thread mapping)
        #pragma unroll
        for (int qi = 0; qi < 4; qi++) {
            float pA = sc[(2 * it) * 4 + qi] * invr[qi];
            float pB = sc[(2 * it + 1) * 4 + qi] * invr[qi];
            sP[(4 * qg + qi) * PPAD + kk]      = pA;
            sP[(4 * qg + qi) * PPAD + 64 + kk] = pB;
        }
        if (it + 1 < NI) { cp_wait<1>(); } else { cp_wait<0>(); }
        __syncthreads();      // sP + V tile visible

        // cooperative vectorized attn store: 16 rows x 128 cols
        if (Ag) {
            #pragma unroll
            for (int jj = 0; jj < 2; jj++) {
                int idx = tid + jj * THREADS;        // 0..511
                int row = idx >> 5;                  // 16 rows
                int c4  = idx & 31;                  // 32 float4/row
                float4 pv = *reinterpret_cast<const float4*>(&sP[row * PPAD + c4 * 4]);
                *reinterpret_cast<float4*>(&Ag[(size_t)row * S + it * IT + c4 * 4]) = pv;
            }
        }

        // PV accumulate (PV thread mapping)
        const float* vb = sKV0 + (it & 1) * SKV_BUF;
        #pragma unroll
        for (int kb = 0; kb < 16; kb++) {
            int k0 = kb * 8 + ks * 2;
            float2 p[4];
            #pragma unroll
            for (int qi = 0; qi < 4; qi++)
                p[qi] = *reinterpret_cast<const float2*>(&sP[(4 * qg + qi) * PPAD + k0]);
            float4 v0 = *reinterpret_cast<const float4*>(&vb[k0 * PAD + d4 * 4]);
            float4 v1 = *reinterpret_cast<const float4*>(&vb[(k0 + 1) * PAD + d4 * 4]);
            float2 v0l = make_float2(v0.x, v0.y), v0h = make_float2(v0.z, v0.w);
            float2 v1l = make_float2(v1.x, v1.y), v1h = make_float2(v1.z, v1.w);
            #pragma unroll
            for (int qi = 0; qi < 4; qi++) {
                float2 pa = make_float2(p[qi].x, p[qi].x);
                float2 pb = make_float2(p[qi].y, p[qi].y);
                acc0[qi] = ffma2(pa, v0l, acc0[qi]);
                acc1[qi] = ffma2(pa, v0h, acc1[qi]);
                acc0[qi] = ffma2(pb, v1l, acc0[qi]);
                acc1[qi] = ffma2(pb, v1h, acc1[qi]);
            }
        }
    }

    // ---- reduce the 4 k-split partials through smem, write context ----
    __syncthreads();
    float* sCtx = sKV0;   // 4*16*64 = 4096 floats
    #pragma unroll
    for (int qi = 0; qi < 4; qi++) {
        float4 r = make_float4(acc0[qi].x, acc0[qi].y, acc1[qi].x, acc1[qi].y);
        *reinterpret_cast<float4*>(&sCtx[((ks * QT + 4 * qg + qi) * D) + d4 * 4]) = r;
    }
    __syncthreads();

    if (Octx) {
        int q  = tid >> 4;
        int dd = tid & 15;
        const float4* base = reinterpret_cast<const float4*>(sCtx);
        float4 r  = base[(0 * QT + q) * 16 + dd];
        float4 c1 = base[(1 * QT + q) * 16 + dd];
        float4 c2 = base[(2 * QT + q) * 16 + dd];
        float4 c3 = base[(3 * QT + q) * 16 + dd];
        r.x += c1.x + c2.x + c3.x;
        r.y += c1.y + c2.y + c3.y;
        r.z += c1.z + c2.z + c3.z;
        r.w += c1.w + c2.w + c3.w;
        float* Cg = Octx + ((size_t)bh * S + q0) * D;
        reinterpret_cast<float4*>(Cg)[q * 16 + dd] = r;
    }
}

} // namespace

extern "C" void kernel_launch(void* const* d_in, const int* in_sizes, int n_in,
                              void* d_out, int out_size) {
    const float*   Q = (const float*)d_in[0];
    const float*   K = (const float*)d_in[1];
    const float*   V = (const float*)d_in[2];
    const uint8_t* M = (const uint8_t*)d_in[3];

    const long long NCTX = 8LL * 16 * 1024 * 64;      // 8388608
    const long long NATT = 8LL * 16 * 1024 * 1024;    // 134217728

    float* ctx  = nullptr;
    float* attn = nullptr;
    if ((long long)out_size >= NCTX + NATT) {
        ctx  = (float*)d_out;                 // tuple order: (context, attn)
        attn = (float*)d_out + NCTX;
    } else if ((long long)out_size == NATT) {
        attn = (float*)d_out;
    } else {
        ctx = (float*)d_out;
    }

    cudaFuncSetAttribute((const void*)sdpa_kernel,
                         cudaFuncAttributeMaxDynamicSharedMemorySize, SMEM_BYTES);

    dim3 grid(S / QT, 8 * 16);
    sdpa_kernel<<<grid, THREADS, SMEM_BYTES>>>(Q, K, V, M, ctx, attn);
}